// round 15
// baseline (speedup 1.0000x reference)
#include <cuda_runtime.h>
#include <cuda_bf16.h>
#include <math.h>
#include <stdint.h>

// ---------------------------------------------------------------------------
// SPDTransform, base-target tensor path (mma.sync bf16):
//   W2t'[n,k] = (W2 @ blockdiag(W))^T folded  -> bf16 hi/lo  [N=4096,K=4096]
//   h  = silu(Y@W1+b1)                        -> bf16 hi/lo  [M=4096,K=4096]
//   Ft = h @ W2'^T + b2'  via 3-product bf16-split mma.sync -> d_out fp32
//   out_b = Ft_b @ Xp_b @ Ft_b^T   (per-sample, Xp = [[x,0],[0,I16]])
// ---------------------------------------------------------------------------

__device__ __nv_bfloat16 g_Ahi[16777216];
__device__ __nv_bfloat16 g_Alo[16777216];
__device__ __nv_bfloat16 g_Bhi[16777216];
__device__ __nv_bfloat16 g_Blo[16777216];
__device__ float         g_b2p[4096];

__device__ __forceinline__ uint32_t smem_u32(const void* p) {
    uint32_t a;
    asm("{ .reg .u64 t; cvta.to.shared.u64 t, %1; cvt.u32.u64 %0, t; }"
        : "=r"(a) : "l"(p));
    return a;
}
__device__ __forceinline__ void cpa16(uint32_t d, const void* s) {
    asm volatile("cp.async.cg.shared.global [%0], [%1], 16;" :: "r"(d), "l"(s)
                 : "memory");
}
__device__ __forceinline__ void ldmx4(uint32_t* r, uint32_t a) {
    asm volatile("ldmatrix.sync.aligned.m8n8.x4.shared.b16 {%0,%1,%2,%3}, [%4];"
                 : "=r"(r[0]), "=r"(r[1]), "=r"(r[2]), "=r"(r[3]) : "r"(a));
}
__device__ __forceinline__ void mma16816(float* c, const uint32_t* a,
                                         uint32_t b0, uint32_t b1) {
    asm volatile(
        "mma.sync.aligned.m16n8k16.row.col.f32.bf16.bf16.f32 "
        "{%0,%1,%2,%3}, {%4,%5,%6,%7}, {%8,%9}, {%0,%1,%2,%3};"
        : "+f"(c[0]), "+f"(c[1]), "+f"(c[2]), "+f"(c[3])
        : "r"(a[0]), "r"(a[1]), "r"(a[2]), "r"(a[3]), "r"(b0), "r"(b1));
}

// Tile 256x128, BK=32 (row = 64 bytes).
// stage layout (bytes): Ahi 16K | Alo 16K | Bhi 8K | Blo 8K = 48K
static constexpr int ST_ALO = 16384;
static constexpr int ST_BHI = 32768;
static constexpr int ST_BLO = 40960;
static constexpr int STAGE  = 49152;
static constexpr int STAGES = 3;
static constexpr int GTC_SMEM = STAGES * STAGE;   // 144 KB

// ---------------------------------------------------------------------------
// C[M=4096, N=4096] = A @ B^T (+bias), A[M,K],B[N,K] bf16 hi/lo, K=4096.
// 3-product split: AhBh + AlBh + AhBl, fp32 accum.
// Tile 256x128, BK=32, 512 thr, 16 warps of 64x32 (4m x 4n).
// 48 HMMA per 12 LDSM per ks step (32 FLOP/smem-byte) — keeps the smem
// crossbar off the critical path. 3-stage cp.async pipeline.
// grid (32 n, 16 m).
// ---------------------------------------------------------------------------
__global__ __launch_bounds__(512, 1)
void gemm_mma(const __nv_bfloat16* __restrict__ Ahi, const __nv_bfloat16* __restrict__ Alo,
              const __nv_bfloat16* __restrict__ Bhi, const __nv_bfloat16* __restrict__ Blo,
              const float* __restrict__ bias, float* __restrict__ C)
{
    extern __shared__ char dsm[];
    const uint32_t base = smem_u32(dsm);

    const int tid  = threadIdx.x;
    const int lane = tid & 31;
    const int wid  = tid >> 5;
    const int warp_m = wid & 3;             // 0..3  -> 64 rows
    const int warp_n = wid >> 2;            // 0..3  -> 32 cols
    const int m0 = blockIdx.y * 256;
    const int n0 = blockIdx.x * 128;

    // swizzle: row r (64B), logical 16B seg s (0..3) -> phys seg s ^ ((r>>1)&3)
    auto load_stage = [&](int kt, int s) {
        const uint32_t sb = base + s * STAGE;
        const int kc = kt * 32;
#pragma unroll
        for (int it = 0; it < 2; ++it) {
            const int idx = tid + it * 512;          // 0..1023: A 256 rows x 4 segs
            const int r = idx >> 2, sg = idx & 3;
            const uint32_t d = (uint32_t)(r * 64 + ((sg ^ ((r >> 1) & 3)) << 4));
            const size_t goA = (size_t)(m0 + r) * 4096 + kc + sg * 8;
            cpa16(sb + d,          Ahi + goA);
            cpa16(sb + ST_ALO + d, Alo + goA);
        }
        {
            const int idx = tid;                     // 0..511: B 128 rows x 4 segs
            const int r = idx >> 2, sg = idx & 3;
            const uint32_t d = (uint32_t)(r * 64 + ((sg ^ ((r >> 1) & 3)) << 4));
            const size_t goB = (size_t)(n0 + r) * 4096 + kc + sg * 8;
            cpa16(sb + ST_BHI + d, Bhi + goB);
            cpa16(sb + ST_BLO + d, Blo + goB);
        }
        asm volatile("cp.async.commit_group;" ::: "memory");
    };

    load_stage(0, 0);
    load_stage(1, 1);

    float acc[4][4][4];
#pragma unroll
    for (int i = 0; i < 4; ++i)
#pragma unroll
        for (int j = 0; j < 4; ++j)
#pragma unroll
            for (int v = 0; v < 4; ++v) acc[i][j][v] = 0.0f;

    const int rA0 = warp_m * 64 + (lane & 15);
    const int rB0 = warp_n * 32 + (lane & 15);
    const int shi = lane >> 4;                    // 16B seg within k16
    const int swz = ((lane & 15) >> 1) & 3;       // row-derived xor

    int sidx = 0;
#pragma unroll 1
    for (int kt = 0; kt < 128; ++kt) {
        asm volatile("cp.async.wait_group 1;" ::: "memory");
        __syncthreads();   // stage kt visible; all warps done with stage kt-1

        if (kt + 2 < 128) {
            int ps = sidx + 2; if (ps >= 3) ps -= 3;
            load_stage(kt + 2, ps);               // overwrites stage of kt-1
        }

        const uint32_t sb = base + sidx * STAGE;
#pragma unroll
        for (int ks = 0; ks < 2; ++ks) {
            const int slog = ks * 2 + shi;
            const uint32_t segoff = (uint32_t)(((slog ^ swz) & 3) << 4);
            uint32_t ah[4][4], al[4][4], bh[2][4], bl[2][4];
#pragma unroll
            for (int mt = 0; mt < 4; ++mt) {
                const uint32_t off = (uint32_t)((rA0 + mt * 16) * 64) + segoff;
                ldmx4(ah[mt], sb + off);
                ldmx4(al[mt], sb + ST_ALO + off);
            }
#pragma unroll
            for (int bt = 0; bt < 2; ++bt) {
                const uint32_t off = (uint32_t)((rB0 + bt * 16) * 64) + segoff;
                ldmx4(bh[bt], sb + ST_BHI + off);
                ldmx4(bl[bt], sb + ST_BLO + off);
            }
#pragma unroll
            for (int mt = 0; mt < 4; ++mt)
#pragma unroll
                for (int nt = 0; nt < 4; ++nt) {
                    const uint32_t h0 = bh[nt >> 1][nt & 1];
                    const uint32_t h1 = bh[nt >> 1][(nt & 1) + 2];
                    mma16816(acc[mt][nt], ah[mt], h0, h1);
                    mma16816(acc[mt][nt], al[mt], h0, h1);
                    mma16816(acc[mt][nt], ah[mt],
                             bl[nt >> 1][nt & 1], bl[nt >> 1][(nt & 1) + 2]);
                }
        }
        ++sidx; if (sidx >= 3) sidx = 0;
    }

    // epilogue: c frag lane l -> rows l/4, l/4+8; cols 2*(l&3)+{0,1}
#pragma unroll
    for (int mt = 0; mt < 4; ++mt)
#pragma unroll
        for (int nt = 0; nt < 4; ++nt) {
            const float* c = acc[mt][nt];
            const int row = m0 + warp_m * 64 + mt * 16 + (lane >> 2);
            const int col = n0 + warp_n * 32 + nt * 8 + 2 * (lane & 3);
            const float bv0 = __ldg(&bias[col]);
            const float bv1 = __ldg(&bias[col + 1]);
            float2 o0 = make_float2(c[0] + bv0, c[1] + bv1);
            float2 o1 = make_float2(c[2] + bv0, c[3] + bv1);
            *(float2*)(C + (size_t)row * 4096 + col)       = o0;
            *(float2*)(C + (size_t)(row + 8) * 4096 + col) = o1;
        }
}

// ---------------------------------------------------------------------------
// h = silu(Y @ W1 + b1), emitted as bf16 hi/lo. FFMA kernel (K=64, tiny).
// ---------------------------------------------------------------------------
__global__ __launch_bounds__(256, 2)
void gemm_h(const float* __restrict__ A, const float* __restrict__ B,
            const float* __restrict__ bias,
            __nv_bfloat16* __restrict__ Chi, __nv_bfloat16* __restrict__ Clo,
            int K, int N)
{
    __shared__ __align__(16) float As[2][16][132];
    __shared__ __align__(16) float Bs[2][16][128];

    const int tid = threadIdx.x;
    const int tx = tid & 15, ty = tid >> 4;
    const long long Arow0 = (long long)blockIdx.y * 128;
    const int Bcol0 = blockIdx.x * 128;

    const int arow = tid >> 2, ac = (tid & 3) << 2;
    const int brow = tid >> 5, bc = (tid & 31) << 2;

    const float* Aptr = A + (Arow0 + arow) * (long long)K + ac;
    const float* Bptr = B + (long long)brow * N + Bcol0 + bc;
    const long long AstepRow = 64LL * K;
    const long long BstepRow = 8LL * N;

    float acc[8][8] = {};
    const int nk = K >> 4;

    float4 a0 = *(const float4*)(Aptr);
    float4 a1 = *(const float4*)(Aptr + AstepRow);
    float4 b0 = *(const float4*)(Bptr);
    float4 b1 = *(const float4*)(Bptr + BstepRow);

    int buf = 0;
    As[0][ac + 0][arow] = a0.x; As[0][ac + 1][arow] = a0.y;
    As[0][ac + 2][arow] = a0.z; As[0][ac + 3][arow] = a0.w;
    As[0][ac + 0][arow + 64] = a1.x; As[0][ac + 1][arow + 64] = a1.y;
    As[0][ac + 2][arow + 64] = a1.z; As[0][ac + 3][arow + 64] = a1.w;
    *(float4*)&Bs[0][brow][bc]     = b0;
    *(float4*)&Bs[0][brow + 8][bc] = b1;
    __syncthreads();

    for (int kt = 1; kt <= nk; ++kt) {
        if (kt < nk) {
            const float* Ap = Aptr + kt * 16;
            a0 = *(const float4*)(Ap);
            a1 = *(const float4*)(Ap + AstepRow);
            const float* Bp = Bptr + (long long)kt * 16 * N;
            b0 = *(const float4*)(Bp);
            b1 = *(const float4*)(Bp + BstepRow);
        }
#pragma unroll
        for (int k = 0; k < 16; ++k) {
            float av[8], bv[8];
            *(float4*)&av[0] = *(const float4*)&As[buf][k][ty * 8];
            *(float4*)&av[4] = *(const float4*)&As[buf][k][ty * 8 + 4];
            *(float4*)&bv[0] = *(const float4*)&Bs[buf][k][tx * 8];
            *(float4*)&bv[4] = *(const float4*)&Bs[buf][k][tx * 8 + 4];
#pragma unroll
            for (int i = 0; i < 8; ++i)
#pragma unroll
                for (int j = 0; j < 8; ++j)
                    acc[i][j] = fmaf(av[i], bv[j], acc[i][j]);
        }
        if (kt < nk) {
            const int nb = buf ^ 1;
            As[nb][ac + 0][arow] = a0.x; As[nb][ac + 1][arow] = a0.y;
            As[nb][ac + 2][arow] = a0.z; As[nb][ac + 3][arow] = a0.w;
            As[nb][ac + 0][arow + 64] = a1.x; As[nb][ac + 1][arow + 64] = a1.y;
            As[nb][ac + 2][arow + 64] = a1.z; As[nb][ac + 3][arow + 64] = a1.w;
            *(float4*)&Bs[nb][brow][bc]     = b0;
            *(float4*)&Bs[nb][brow + 8][bc] = b1;
        }
        __syncthreads();
        buf ^= 1;
    }

    const int col0 = Bcol0 + tx * 8;
#pragma unroll
    for (int i = 0; i < 8; ++i) {
        const long long row = Arow0 + ty * 8 + i;
        union { __nv_bfloat16 h[8]; uint4 u; } ph, pl;
#pragma unroll
        for (int j = 0; j < 8; ++j) {
            float v = acc[i][j] + __ldg(&bias[col0 + j]);
            v = v / (1.0f + expf(-v));                 // silu
            __nv_bfloat16 hi = __float2bfloat16(v);
            ph.h[j] = hi;
            pl.h[j] = __float2bfloat16(v - __bfloat162float(hi));
        }
        *(uint4*)&Chi[row * N + col0] = ph.u;
        *(uint4*)&Clo[row * N + col0] = pl.u;
    }
}

// ---------------------------------------------------------------------------
// Fold + transpose: B[n=64i+j, k=m] = sum_t W2[m,64i+t] * W[j*64+t], bf16 hi/lo
// ---------------------------------------------------------------------------
__global__ __launch_bounds__(256)
void fold_w2t(const float* __restrict__ W2, const float* __restrict__ W,
              __nv_bfloat16* __restrict__ Bhi, __nv_bfloat16* __restrict__ Blo)
{
    __shared__ float W2s[64][65];
    __shared__ float Ws[64][64];
    const int i = blockIdx.x;
    const int m0 = blockIdx.y * 64;
    const int tid = threadIdx.x;

    for (int p = tid; p < 4096; p += 256) {
        const int mm = p >> 6, k = p & 63;
        W2s[mm][k] = W2[(size_t)(m0 + mm) * 4096 + i * 64 + k];
    }
    for (int p = tid; p < 4096; p += 256) Ws[p >> 6][p & 63] = W[p];
    __syncthreads();

    const int mm = tid & 63, jg = tid >> 6;
#pragma unroll 1
    for (int jj = 0; jj < 16; ++jj) {
        const int j = jg * 16 + jj;
        float acc = 0.0f;
#pragma unroll
        for (int k = 0; k < 64; ++k) acc = fmaf(W2s[mm][k], Ws[j][k], acc);
        const size_t o = (size_t)(i * 64 + j) * 4096 + m0 + mm;
        __nv_bfloat16 hi = __float2bfloat16(acc);
        Bhi[o] = hi;
        Blo[o] = __float2bfloat16(acc - __bfloat162float(hi));
    }
}

// b2'[64i+j] = sum_k b2[64i+k] * W[j*64+k]
__global__ void fold_b2(const float* __restrict__ b2,
                        const float* __restrict__ W,
                        float* __restrict__ b2p)
{
    const int p = blockIdx.x * 256 + threadIdx.x;
    const int i = p >> 6, j = p & 63;
    float s = 0.0f;
    for (int k = 0; k < 64; ++k)
        s = fmaf(__ldg(&b2[i * 64 + k]), __ldg(&W[j * 64 + k]), s);
    b2p[p] = s;
}

// ---------------------------------------------------------------------------
// Per-sample: out_b = Ft_b @ Xp_b @ Ft_b^T,  Xp = [[x,0],[0,I16]]  (in-place)
// ---------------------------------------------------------------------------
__global__ __launch_bounds__(256)
void spd_out(const float* __restrict__ X, float* __restrict__ F)
{
    __shared__ float Fs[64 * 65];
    __shared__ float Xs[48 * 49];
    __shared__ float Gs[64 * 64];

    const int b = blockIdx.x;
    const int tid = threadIdx.x;

    const float* Fg = F + (long long)b * 4096;
    for (int p = tid; p < 4096; p += 256)
        Fs[(p >> 6) * 65 + (p & 63)] = Fg[p];
    const float* Xg = X + (long long)b * 2304;
    for (int p = tid; p < 2304; p += 256)
        Xs[(p / 48) * 49 + (p % 48)] = Xg[p];
    __syncthreads();

    const int tx = tid & 15, ty = tid >> 4;
    const int i0 = ty * 4, k0 = tx * 4;

    float g[4][4] = {};
    if (tx < 12) {
        for (int j = 0; j < 48; ++j) {
            float a[4], xb[4];
#pragma unroll
            for (int u = 0; u < 4; ++u) a[u]  = Fs[(i0 + u) * 65 + j];
#pragma unroll
            for (int u = 0; u < 4; ++u) xb[u] = Xs[j * 49 + k0 + u];
#pragma unroll
            for (int u = 0; u < 4; ++u)
#pragma unroll
                for (int v = 0; v < 4; ++v) g[u][v] = fmaf(a[u], xb[v], g[u][v]);
        }
    } else {
#pragma unroll
        for (int u = 0; u < 4; ++u)
#pragma unroll
            for (int v = 0; v < 4; ++v) g[u][v] = Fs[(i0 + u) * 65 + k0 + v];
    }
#pragma unroll
    for (int u = 0; u < 4; ++u)
#pragma unroll
        for (int v = 0; v < 4; ++v) Gs[(i0 + u) * 64 + k0 + v] = g[u][v];
    __syncthreads();

    const int l0 = tx * 4;
    float acc[4][4] = {};
    for (int k = 0; k < 64; ++k) {
        float a[4], bb[4];
#pragma unroll
        for (int u = 0; u < 4; ++u) a[u]  = Gs[(i0 + u) * 64 + k];
#pragma unroll
        for (int u = 0; u < 4; ++u) bb[u] = Fs[(l0 + u) * 65 + k];
#pragma unroll
        for (int u = 0; u < 4; ++u)
#pragma unroll
            for (int v = 0; v < 4; ++v) acc[u][v] = fmaf(a[u], bb[v], acc[u][v]);
    }

    float* Og = F + (long long)b * 4096;
#pragma unroll
    for (int u = 0; u < 4; ++u) {
        float4 o = make_float4(acc[u][0], acc[u][1], acc[u][2], acc[u][3]);
        *(float4*)&Og[(i0 + u) * 64 + l0] = o;
    }
}

// ---------------------------------------------------------------------------
extern "C" void kernel_launch(void* const* d_in, const int* in_sizes, int n_in,
                              void* d_out, int out_size)
{
    const float* x  = (const float*)d_in[0];  // [4096,48,48]
    const float* Y  = (const float*)d_in[2];  // [4096,64]
    const float* W  = (const float*)d_in[3];  // [64,64]
    const float* W1 = (const float*)d_in[4];  // [64,4096]
    const float* b1 = (const float*)d_in[5];  // [4096]
    const float* W2 = (const float*)d_in[6];  // [4096,4096]
    const float* b2 = (const float*)d_in[7];  // [4096]
    float* out = (float*)d_out;               // [4096,64,64]

    __nv_bfloat16 *ahi, *alo, *bhi, *blo;
    float* b2p;
    cudaGetSymbolAddress((void**)&ahi, g_Ahi);
    cudaGetSymbolAddress((void**)&alo, g_Alo);
    cudaGetSymbolAddress((void**)&bhi, g_Bhi);
    cudaGetSymbolAddress((void**)&blo, g_Blo);
    cudaGetSymbolAddress((void**)&b2p, g_b2p);

    cudaFuncSetAttribute(gemm_mma, cudaFuncAttributeMaxDynamicSharedMemorySize,
                         GTC_SMEM);

    fold_w2t<<<dim3(64, 64), 256>>>(W2, W, bhi, blo);
    fold_b2<<<16, 256>>>(b2, W, b2p);
    gemm_h<<<dim3(32, 32), 256>>>(Y, W1, b1, ahi, alo, 64, 4096);
    gemm_mma<<<dim3(32, 16), 512, GTC_SMEM>>>(ahi, alo, bhi, blo, b2p, out);
    spd_out<<<4096, 256>>>(x, out);
}

// round 16
// speedup vs baseline: 1.2384x; 1.2384x over previous
#include <cuda_runtime.h>
#include <cuda_bf16.h>
#include <math.h>
#include <stdint.h>

// ---------------------------------------------------------------------------
// SPDTransform, base-target tensor path (mma.sync bf16):
//   W2t'[n,k] = (W2 @ blockdiag(W))^T folded  -> bf16 hi/lo  [N=4096,K=4096]
//   h  = silu(Y@W1+b1)                        -> bf16 hi/lo  [M=4096,K=4096]
//   Ft = h @ W2'^T + b2'  via 3-product bf16-split mma.sync -> d_out fp32
//   out_b = Ft_b @ Xp_b @ Ft_b^T   (per-sample, Xp = [[x,0],[0,I16]])
// ---------------------------------------------------------------------------

__device__ __nv_bfloat16 g_Ahi[16777216];
__device__ __nv_bfloat16 g_Alo[16777216];
__device__ __nv_bfloat16 g_Bhi[16777216];
__device__ __nv_bfloat16 g_Blo[16777216];
__device__ float         g_b2p[4096];

__device__ __forceinline__ uint32_t smem_u32(const void* p) {
    uint32_t a;
    asm("{ .reg .u64 t; cvta.to.shared.u64 t, %1; cvt.u32.u64 %0, t; }"
        : "=r"(a) : "l"(p));
    return a;
}
__device__ __forceinline__ void cpa16(uint32_t d, const void* s) {
    asm volatile("cp.async.cg.shared.global [%0], [%1], 16;" :: "r"(d), "l"(s)
                 : "memory");
}
__device__ __forceinline__ void ldmx4(uint32_t* r, uint32_t a) {
    asm volatile("ldmatrix.sync.aligned.m8n8.x4.shared.b16 {%0,%1,%2,%3}, [%4];"
                 : "=r"(r[0]), "=r"(r[1]), "=r"(r[2]), "=r"(r[3]) : "r"(a));
}
__device__ __forceinline__ void mma16816(float* c, const uint32_t* a,
                                         uint32_t b0, uint32_t b1) {
    asm volatile(
        "mma.sync.aligned.m16n8k16.row.col.f32.bf16.bf16.f32 "
        "{%0,%1,%2,%3}, {%4,%5,%6,%7}, {%8,%9}, {%0,%1,%2,%3};"
        : "+f"(c[0]), "+f"(c[1]), "+f"(c[2]), "+f"(c[3])
        : "r"(a[0]), "r"(a[1]), "r"(a[2]), "r"(a[3]), "r"(b0), "r"(b1));
}

// ---- packed f32x2 helpers (measured 2x FFMA throughput in R1) -------------
__device__ __forceinline__ unsigned long long pack2(float x) {
    unsigned long long r;
    unsigned int xi = __float_as_uint(x);
    asm("mov.b64 %0, {%1, %1};" : "=l"(r) : "r"(xi));
    return r;
}
__device__ __forceinline__ unsigned long long packxy(float x, float y) {
    unsigned long long r;
    asm("mov.b64 %0, {%1, %2};" : "=l"(r) : "r"(__float_as_uint(x)),
        "r"(__float_as_uint(y)));
    return r;
}
__device__ __forceinline__ unsigned long long fma2(unsigned long long a,
                                                   unsigned long long b,
                                                   unsigned long long c) {
    unsigned long long d;
    asm("fma.rn.f32x2 %0, %1, %2, %3;" : "=l"(d) : "l"(a), "l"(b), "l"(c));
    return d;
}
__device__ __forceinline__ float2 unpack2(unsigned long long v) {
    unsigned int lo, hi;
    asm("mov.b64 {%0, %1}, %2;" : "=r"(lo), "=r"(hi) : "l"(v));
    float2 f; f.x = __uint_as_float(lo); f.y = __uint_as_float(hi);
    return f;
}

// Tile 128x128, BK=64 (row = 128 bytes).
// stage layout (bytes): Ahi 16K | Alo 16K | Bhi 16K | Blo 16K = 64K
static constexpr int ST_ALO = 16384;
static constexpr int ST_BHI = 32768;
static constexpr int ST_BLO = 49152;
static constexpr int STAGE  = 65536;
static constexpr int STAGES = 3;
static constexpr int GTC_SMEM = STAGES * STAGE;   // 192 KB

// ---------------------------------------------------------------------------
// gemm_mma: IDENTICAL to R14 (best measured: 1029us, tensor 65.9%).
// ---------------------------------------------------------------------------
__global__ __launch_bounds__(512, 1)
void gemm_mma(const __nv_bfloat16* __restrict__ Ahi, const __nv_bfloat16* __restrict__ Alo,
              const __nv_bfloat16* __restrict__ Bhi, const __nv_bfloat16* __restrict__ Blo,
              const float* __restrict__ bias, float* __restrict__ C)
{
    extern __shared__ char dsm[];
    const uint32_t base = smem_u32(dsm);

    const int tid  = threadIdx.x;
    const int lane = tid & 31;
    const int wid  = tid >> 5;
    const int warp_m = wid & 3;             // 0..3  -> 32 rows
    const int warp_n = wid >> 2;            // 0..3  -> 32 cols
    const int m0 = blockIdx.y * 128;
    const int n0 = blockIdx.x * 128;

    // swizzle: row r (128B), logical 16B seg s (0..7) -> phys seg s ^ (r&7)
    auto load_stage = [&](int kt, int s) {
        const uint32_t sb = base + s * STAGE;
        const int kc = kt * 64;
#pragma unroll
        for (int it = 0; it < 2; ++it) {
            const int idx = tid + it * 512;          // 0..1023
            const int r = idx >> 3, sg = idx & 7;
            const uint32_t d = (uint32_t)(r * 128 + ((sg ^ (r & 7)) << 4));
            const size_t goA = (size_t)(m0 + r) * 4096 + kc + sg * 8;
            const size_t goB = (size_t)(n0 + r) * 4096 + kc + sg * 8;
            cpa16(sb + d,          Ahi + goA);
            cpa16(sb + ST_ALO + d, Alo + goA);
            cpa16(sb + ST_BHI + d, Bhi + goB);
            cpa16(sb + ST_BLO + d, Blo + goB);
        }
        asm volatile("cp.async.commit_group;" ::: "memory");
    };

    load_stage(0, 0);
    load_stage(1, 1);

    float acc[2][4][4];
#pragma unroll
    for (int i = 0; i < 2; ++i)
#pragma unroll
        for (int j = 0; j < 4; ++j)
#pragma unroll
            for (int v = 0; v < 4; ++v) acc[i][j][v] = 0.0f;

    const int rA0 = warp_m * 32 + (lane & 15);
    const int rB0 = warp_n * 32 + (lane & 15);
    const uint32_t offA0 = (uint32_t)(rA0 * 128);
    const uint32_t offA1 = (uint32_t)((rA0 + 16) * 128);
    const uint32_t offB0 = (uint32_t)(rB0 * 128);
    const uint32_t offB1 = (uint32_t)((rB0 + 16) * 128);
    const int shi = lane >> 4;
    const int swz = (lane & 15) & 7;

    uint32_t ah[2][2][4], al[2][2][4], bh[2][2][4], bl[2][2][4];

    auto load_frags = [&](uint32_t sb, int ks, int fb) {
        const int slog = ks * 2 + shi;
        const uint32_t segoff = (uint32_t)(((slog ^ swz) & 7) << 4);
        ldmx4(ah[fb][0], sb + offA0 + segoff);
        ldmx4(ah[fb][1], sb + offA1 + segoff);
        ldmx4(al[fb][0], sb + ST_ALO + offA0 + segoff);
        ldmx4(al[fb][1], sb + ST_ALO + offA1 + segoff);
        ldmx4(bh[fb][0], sb + ST_BHI + offB0 + segoff);
        ldmx4(bh[fb][1], sb + ST_BHI + offB1 + segoff);
        ldmx4(bl[fb][0], sb + ST_BLO + offB0 + segoff);
        ldmx4(bl[fb][1], sb + ST_BLO + offB1 + segoff);
    };
    auto do_mmas = [&](int fb) {
#pragma unroll
        for (int mt = 0; mt < 2; ++mt)
#pragma unroll
            for (int nt = 0; nt < 4; ++nt) {
                const uint32_t h0 = bh[fb][nt >> 1][nt & 1];
                const uint32_t h1 = bh[fb][nt >> 1][(nt & 1) + 2];
                mma16816(acc[mt][nt], ah[fb][mt], h0, h1);
                mma16816(acc[mt][nt], al[fb][mt], h0, h1);
                mma16816(acc[mt][nt], ah[fb][mt],
                         bl[fb][nt >> 1][nt & 1], bl[fb][nt >> 1][(nt & 1) + 2]);
            }
    };

    int sidx = 0;
#pragma unroll 1
    for (int kt = 0; kt < 64; ++kt) {
        asm volatile("cp.async.wait_group 1;" ::: "memory");
        __syncthreads();

        if (kt + 2 < 64) {
            int ps = sidx + 2; if (ps >= 3) ps -= 3;
            load_stage(kt + 2, ps);
        }

        const uint32_t sb = base + sidx * STAGE;
        load_frags(sb, 0, 0);
#pragma unroll
        for (int ks = 0; ks < 4; ++ks) {
            if (ks < 3) load_frags(sb, ks + 1, (ks + 1) & 1);
            do_mmas(ks & 1);
        }
        ++sidx; if (sidx >= 3) sidx = 0;
    }

#pragma unroll
    for (int mt = 0; mt < 2; ++mt)
#pragma unroll
        for (int nt = 0; nt < 4; ++nt) {
            const float* c = acc[mt][nt];
            const int row = m0 + warp_m * 32 + mt * 16 + (lane >> 2);
            const int col = n0 + warp_n * 32 + nt * 8 + 2 * (lane & 3);
            const float bv0 = __ldg(&bias[col]);
            const float bv1 = __ldg(&bias[col + 1]);
            float2 o0 = make_float2(c[0] + bv0, c[1] + bv1);
            float2 o1 = make_float2(c[2] + bv0, c[3] + bv1);
            *(float2*)(C + (size_t)row * 4096 + col)       = o0;
            *(float2*)(C + (size_t)(row + 8) * 4096 + col) = o1;
        }
}

// ---------------------------------------------------------------------------
// h = silu(Y @ W1 + b1), bf16 hi/lo out. K=64. f32x2 accumulators.
// ---------------------------------------------------------------------------
__global__ __launch_bounds__(256, 2)
void gemm_h(const float* __restrict__ A, const float* __restrict__ B,
            const float* __restrict__ bias,
            __nv_bfloat16* __restrict__ Chi, __nv_bfloat16* __restrict__ Clo,
            int K, int N)
{
    __shared__ __align__(16) float As[2][16][132];
    __shared__ __align__(16) float Bs[2][16][128];

    const int tid = threadIdx.x;
    const int tx = tid & 15, ty = tid >> 4;
    const long long Arow0 = (long long)blockIdx.y * 128;
    const int Bcol0 = blockIdx.x * 128;

    const int arow = tid >> 2, ac = (tid & 3) << 2;
    const int brow = tid >> 5, bc = (tid & 31) << 2;

    const float* Aptr = A + (Arow0 + arow) * (long long)K + ac;
    const float* Bptr = B + (long long)brow * N + Bcol0 + bc;
    const long long AstepRow = 64LL * K;
    const long long BstepRow = 8LL * N;

    unsigned long long acc2[8][4];
#pragma unroll
    for (int i = 0; i < 8; ++i)
#pragma unroll
        for (int j = 0; j < 4; ++j) acc2[i][j] = 0ull;
    const int nk = K >> 4;

    float4 a0 = *(const float4*)(Aptr);
    float4 a1 = *(const float4*)(Aptr + AstepRow);
    float4 b0 = *(const float4*)(Bptr);
    float4 b1 = *(const float4*)(Bptr + BstepRow);

    int buf = 0;
    As[0][ac + 0][arow] = a0.x; As[0][ac + 1][arow] = a0.y;
    As[0][ac + 2][arow] = a0.z; As[0][ac + 3][arow] = a0.w;
    As[0][ac + 0][arow + 64] = a1.x; As[0][ac + 1][arow + 64] = a1.y;
    As[0][ac + 2][arow + 64] = a1.z; As[0][ac + 3][arow + 64] = a1.w;
    *(float4*)&Bs[0][brow][bc]     = b0;
    *(float4*)&Bs[0][brow + 8][bc] = b1;
    __syncthreads();

    for (int kt = 1; kt <= nk; ++kt) {
        if (kt < nk) {
            const float* Ap = Aptr + kt * 16;
            a0 = *(const float4*)(Ap);
            a1 = *(const float4*)(Ap + AstepRow);
            const float* Bp = Bptr + (long long)kt * 16 * N;
            b0 = *(const float4*)(Bp);
            b1 = *(const float4*)(Bp + BstepRow);
        }
#pragma unroll
        for (int k = 0; k < 16; ++k) {
            float av[8];
            *(float4*)&av[0] = *(const float4*)&As[buf][k][ty * 8];
            *(float4*)&av[4] = *(const float4*)&As[buf][k][ty * 8 + 4];
            ulonglong2 bp0 = *(const ulonglong2*)&Bs[buf][k][tx * 8];
            ulonglong2 bp1 = *(const ulonglong2*)&Bs[buf][k][tx * 8 + 4];
#pragma unroll
            for (int i = 0; i < 8; ++i) {
                const unsigned long long ap = pack2(av[i]);
                acc2[i][0] = fma2(ap, bp0.x, acc2[i][0]);
                acc2[i][1] = fma2(ap, bp0.y, acc2[i][1]);
                acc2[i][2] = fma2(ap, bp1.x, acc2[i][2]);
                acc2[i][3] = fma2(ap, bp1.y, acc2[i][3]);
            }
        }
        if (kt < nk) {
            const int nb = buf ^ 1;
            As[nb][ac + 0][arow] = a0.x; As[nb][ac + 1][arow] = a0.y;
            As[nb][ac + 2][arow] = a0.z; As[nb][ac + 3][arow] = a0.w;
            As[nb][ac + 0][arow + 64] = a1.x; As[nb][ac + 1][arow + 64] = a1.y;
            As[nb][ac + 2][arow + 64] = a1.z; As[nb][ac + 3][arow + 64] = a1.w;
            *(float4*)&Bs[nb][brow][bc]     = b0;
            *(float4*)&Bs[nb][brow + 8][bc] = b1;
        }
        __syncthreads();
        buf ^= 1;
    }

    const int col0 = Bcol0 + tx * 8;
#pragma unroll
    for (int i = 0; i < 8; ++i) {
        const long long row = Arow0 + ty * 8 + i;
        union { __nv_bfloat16 h[8]; uint4 u; } ph, pl;
#pragma unroll
        for (int j4 = 0; j4 < 4; ++j4) {
            float2 p = unpack2(acc2[i][j4]);
            float vv[2] = {p.x, p.y};
#pragma unroll
            for (int t = 0; t < 2; ++t) {
                const int j = j4 * 2 + t;
                float v = vv[t] + __ldg(&bias[col0 + j]);
                v = v / (1.0f + expf(-v));             // silu
                __nv_bfloat16 hi = __float2bfloat16(v);
                ph.h[j] = hi;
                pl.h[j] = __float2bfloat16(v - __bfloat162float(hi));
            }
        }
        *(uint4*)&Chi[row * N + col0] = ph.u;
        *(uint4*)&Clo[row * N + col0] = pl.u;
    }
}

// ---------------------------------------------------------------------------
// Fold + transpose: B[n=64i+j, k=m] = sum_t W2[m,64i+t] * W[j*64+t].
// Register-cached W2 row, 8B packed Ws reads, f32x2 accumulation over k-pairs.
// ---------------------------------------------------------------------------
__global__ __launch_bounds__(256)
void fold_w2t(const float* __restrict__ W2, const float* __restrict__ W,
              __nv_bfloat16* __restrict__ Bhi, __nv_bfloat16* __restrict__ Blo)
{
    __shared__ __align__(8) float W2s[64][66];   // even stride: 8B-aligned rows
    __shared__ __align__(8) float Ws[64][64];    // contiguous rows (broadcast reads)
    const int i = blockIdx.x;
    const int m0 = blockIdx.y * 64;
    const int tid = threadIdx.x;

    for (int p = tid; p < 4096; p += 256) {
        const int mm = p >> 6, k = p & 63;
        W2s[mm][k] = W2[(size_t)(m0 + mm) * 4096 + i * 64 + k];
    }
    for (int p = tid; p < 4096; p += 256) Ws[p >> 6][p & 63] = W[p];
    __syncthreads();

    const int mm = tid & 63, jg = tid >> 6;
    unsigned long long acc2[16];
#pragma unroll
    for (int j = 0; j < 16; ++j) acc2[j] = 0ull;

#pragma unroll
    for (int c = 0; c < 4; ++c) {
        unsigned long long ar2[8];
#pragma unroll
        for (int kk = 0; kk < 8; ++kk)
            ar2[kk] = *(const unsigned long long*)&W2s[mm][c * 16 + kk * 2];
#pragma unroll
        for (int jj = 0; jj < 16; ++jj) {
            const int j = jg * 16 + jj;
            const unsigned long long* wrow =
                (const unsigned long long*)&Ws[j][c * 16];
#pragma unroll
            for (int kk = 0; kk < 8; ++kk)
                acc2[jj] = fma2(ar2[kk], wrow[kk], acc2[jj]);
        }
    }

#pragma unroll
    for (int jj = 0; jj < 16; ++jj) {
        const int j = jg * 16 + jj;
        float2 p = unpack2(acc2[jj]);
        const float acc = p.x + p.y;
        const size_t o = (size_t)(i * 64 + j) * 4096 + m0 + mm;
        __nv_bfloat16 hi = __float2bfloat16(acc);
        Bhi[o] = hi;
        Blo[o] = __float2bfloat16(acc - __bfloat162float(hi));
    }
}

// b2'[64i+j] = sum_k b2[64i+k] * W[j*64+k]
__global__ void fold_b2(const float* __restrict__ b2,
                        const float* __restrict__ W,
                        float* __restrict__ b2p)
{
    const int p = blockIdx.x * 256 + threadIdx.x;
    const int i = p >> 6, j = p & 63;
    float s = 0.0f;
    for (int k = 0; k < 64; ++k)
        s = fmaf(__ldg(&b2[i * 64 + k]), __ldg(&W[j * 64 + k]), s);
    b2p[p] = s;
}

// ---------------------------------------------------------------------------
// Per-sample: out_b = Ft_b @ Xp_b @ Ft_b^T,  Xp = [[x,0],[0,I16]]  (in-place)
// f32x2 accumulators; Gs stride 65 (kills 16-way conflict of stride 64).
// ---------------------------------------------------------------------------
__global__ __launch_bounds__(256)
void spd_out(const float* __restrict__ X, float* __restrict__ F)
{
    __shared__ float Fs[64 * 65];
    __shared__ float Xs[48 * 49];
    __shared__ float Gs[64 * 65];

    const int b = blockIdx.x;
    const int tid = threadIdx.x;

    const float* Fg = F + (long long)b * 4096;
    for (int p = tid; p < 4096; p += 256)
        Fs[(p >> 6) * 65 + (p & 63)] = Fg[p];
    const float* Xg = X + (long long)b * 2304;
    for (int p = tid; p < 2304; p += 256)
        Xs[(p / 48) * 49 + (p % 48)] = Xg[p];
    __syncthreads();

    const int tx = tid & 15, ty = tid >> 4;
    const int i0 = ty * 4, k0 = tx * 4;

    // G[i,k] = sum_{j<48} Ft[i,j] x[j,k] (k<48); Ft[i,k] (k>=48)
    unsigned long long g2[4][2];
#pragma unroll
    for (int u = 0; u < 4; ++u) { g2[u][0] = 0ull; g2[u][1] = 0ull; }
    if (tx < 12) {
        for (int j = 0; j < 48; ++j) {
            float a[4], xb[4];
#pragma unroll
            for (int u = 0; u < 4; ++u) a[u]  = Fs[(i0 + u) * 65 + j];
#pragma unroll
            for (int u = 0; u < 4; ++u) xb[u] = Xs[j * 49 + k0 + u];
            const unsigned long long xp0 = packxy(xb[0], xb[1]);
            const unsigned long long xp1 = packxy(xb[2], xb[3]);
#pragma unroll
            for (int u = 0; u < 4; ++u) {
                const unsigned long long ap = pack2(a[u]);
                g2[u][0] = fma2(ap, xp0, g2[u][0]);
                g2[u][1] = fma2(ap, xp1, g2[u][1]);
            }
        }
    } else {
#pragma unroll
        for (int u = 0; u < 4; ++u) {
            g2[u][0] = packxy(Fs[(i0 + u) * 65 + k0],
                              Fs[(i0 + u) * 65 + k0 + 1]);
            g2[u][1] = packxy(Fs[(i0 + u) * 65 + k0 + 2],
                              Fs[(i0 + u) * 65 + k0 + 3]);
        }
    }
#pragma unroll
    for (int u = 0; u < 4; ++u) {
        float2 p0 = unpack2(g2[u][0]);
        float2 p1 = unpack2(g2[u][1]);
        Gs[(i0 + u) * 65 + k0 + 0] = p0.x;
        Gs[(i0 + u) * 65 + k0 + 1] = p0.y;
        Gs[(i0 + u) * 65 + k0 + 2] = p1.x;
        Gs[(i0 + u) * 65 + k0 + 3] = p1.y;
    }
    __syncthreads();

    // out[i,l] = sum_k G[i,k] * Ft[l,k]
    const int l0 = tx * 4;
    unsigned long long acc2[4][2];
#pragma unroll
    for (int u = 0; u < 4; ++u) { acc2[u][0] = 0ull; acc2[u][1] = 0ull; }
    for (int k = 0; k < 64; ++k) {
        float a[4], bb[4];
#pragma unroll
        for (int u = 0; u < 4; ++u) a[u]  = Gs[(i0 + u) * 65 + k];
#pragma unroll
        for (int u = 0; u < 4; ++u) bb[u] = Fs[(l0 + u) * 65 + k];
        const unsigned long long bp0 = packxy(bb[0], bb[1]);
        const unsigned long long bp1 = packxy(bb[2], bb[3]);
#pragma unroll
        for (int u = 0; u < 4; ++u) {
            const unsigned long long ap = pack2(a[u]);
            acc2[u][0] = fma2(ap, bp0, acc2[u][0]);
            acc2[u][1] = fma2(ap, bp1, acc2[u][1]);
        }
    }

    float* Og = F + (long long)b * 4096;
#pragma unroll
    for (int u = 0; u < 4; ++u) {
        float2 p0 = unpack2(acc2[u][0]);
        float2 p1 = unpack2(acc2[u][1]);
        float4 o = make_float4(p0.x, p0.y, p1.x, p1.y);
        *(float4*)&Og[(i0 + u) * 64 + l0] = o;
    }
}

// ---------------------------------------------------------------------------
extern "C" void kernel_launch(void* const* d_in, const int* in_sizes, int n_in,
                              void* d_out, int out_size)
{
    const float* x  = (const float*)d_in[0];  // [4096,48,48]
    const float* Y  = (const float*)d_in[2];  // [4096,64]
    const float* W  = (const float*)d_in[3];  // [64,64]
    const float* W1 = (const float*)d_in[4];  // [64,4096]
    const float* b1 = (const float*)d_in[5];  // [4096]
    const float* W2 = (const float*)d_in[6];  // [4096,4096]
    const float* b2 = (const float*)d_in[7];  // [4096]
    float* out = (float*)d_out;               // [4096,64,64]

    __nv_bfloat16 *ahi, *alo, *bhi, *blo;
    float* b2p;
    cudaGetSymbolAddress((void**)&ahi, g_Ahi);
    cudaGetSymbolAddress((void**)&alo, g_Alo);
    cudaGetSymbolAddress((void**)&bhi, g_Bhi);
    cudaGetSymbolAddress((void**)&blo, g_Blo);
    cudaGetSymbolAddress((void**)&b2p, g_b2p);

    cudaFuncSetAttribute(gemm_mma, cudaFuncAttributeMaxDynamicSharedMemorySize,
                         GTC_SMEM);

    fold_w2t<<<dim3(64, 64), 256>>>(W2, W, bhi, blo);
    fold_b2<<<16, 256>>>(b2, W, b2p);
    gemm_h<<<dim3(32, 32), 256>>>(Y, W1, b1, ahi, alo, 64, 4096);
    gemm_mma<<<dim3(32, 32), 512, GTC_SMEM>>>(ahi, alo, bhi, blo, b2p, out);
    spd_out<<<4096, 256>>>(x, out);
}